// round 5
// baseline (speedup 1.0000x reference)
#include <cuda_runtime.h>
#include <cstdint>

#define BB 2
#define NN 32768
#define KK 16
#define BN (BB*NN)

// Scratch (device globals; no allocation allowed)
__device__ float g_featT[(size_t)BN*64];  // net_new, (B*N, 64) row-major
__device__ float g_g1[(size_t)BN*64];     // W_sc1[:, :64] @ net_new + b_sc1

// ---------------------------------------------------------------------------
// Phase 1: MotionEncoder + ConvGRU.  Warp handles 4 consecutive points.
// smem: wz/wr/wq (64x196), w_me (61x132), w_corr (64x68), biases, 32 point bufs
// ---------------------------------------------------------------------------
__global__ __launch_bounds__(256, 1) void phase1_kernel(
    const float* __restrict__ net, const float* __restrict__ inp,
    const float* __restrict__ corr, const float* __restrict__ flow,
    const float* __restrict__ w_corr, const float* __restrict__ b_corr,
    const float* __restrict__ w_flow, const float* __restrict__ b_flow,
    const float* __restrict__ w_me, const float* __restrict__ b_me,
    const float* __restrict__ wz, const float* __restrict__ bz,
    const float* __restrict__ wr, const float* __restrict__ br,
    const float* __restrict__ wq, const float* __restrict__ bq)
{
    extern __shared__ float sm[];
    float* s_wz   = sm;                  // 64*196
    float* s_wr   = s_wz  + 64*196;
    float* s_wq   = s_wr  + 64*196;
    float* s_wme  = s_wq  + 64*196;      // 61*132
    float* s_wc   = s_wme + 61*132;      // 64*68
    float* s_bias = s_wc  + 64*68;       // 384: [bz][br][bq][b_corr][b_flow][b_me]
    float* s_buf  = s_bias + 384;        // 32 points * 192

    const int tid = threadIdx.x;
    for (int i = tid; i < 64*192; i += 256) {
        int o = i / 192, c = i - o*192;
        s_wz[o*196+c] = wz[i]; s_wr[o*196+c] = wr[i]; s_wq[o*196+c] = wq[i];
    }
    for (int i = tid; i < 61*128; i += 256) { int o=i/128, c=i-o*128; s_wme[o*132+c]=w_me[i]; }
    for (int i = tid; i < 64*64;  i += 256) { int o=i>>6,  c=i&63;    s_wc[o*68+c]=w_corr[i]; }
    if (tid < 64) {
        s_bias[tid]     = bz[tid];
        s_bias[64+tid]  = br[tid];
        s_bias[128+tid] = bq[tid];
        s_bias[192+tid] = b_corr[tid];
        s_bias[256+tid] = b_flow[tid];
        s_bias[320+tid] = (tid < 61) ? b_me[tid] : 0.f;
    }
    __syncthreads();

    const int warp = tid >> 5, lane = tid & 31;
    const int o1 = lane, o2 = lane + 32;
    float* bA = s_buf + warp * 4 * 192;

    const float wf0a = __ldg(w_flow + o1*3 + 0), wf1a = __ldg(w_flow + o1*3 + 1), wf2a = __ldg(w_flow + o1*3 + 2);
    const float wf0b = __ldg(w_flow + o2*3 + 0), wf1b = __ldg(w_flow + o2*3 + 1), wf2b = __ldg(w_flow + o2*3 + 2);

    for (int task = blockIdx.x*8 + warp; task < BN/4; task += gridDim.x*8) {
        const int p0 = task * 4;
        const int b  = p0 >> 15;          // N = 32768 = 2^15
        const int n0 = p0 & (NN - 1);
        const float* cbase = corr + (size_t)b*64*NN + n0;
        const float* nbase = net  + (size_t)b*64*NN + n0;
        const float* ibase = inp  + (size_t)b*64*NN + n0;
        const float* fbase = flow + ((size_t)b*NN + n0)*3;

        // --- load corr (64ch x 4pts): 256 elems, 8 lane-iterations ---
        #pragma unroll
        for (int t = 0; t < 8; t++) {
            int idx = t*32 + lane;
            int c = idx >> 2, j = idx & 3;
            bA[j*192 + c] = __ldg(cbase + (size_t)c*NN + j);
        }
        __syncwarp();

        // --- cor = relu(w_corr @ corr + b) ---
        float c1[4], c2[4];
        #pragma unroll
        for (int j = 0; j < 4; j++) { c1[j] = s_bias[192+o1]; c2[j] = s_bias[192+o2]; }
        #pragma unroll
        for (int c = 0; c < 64; c += 4) {
            float4 wa = *(const float4*)(s_wc + o1*68 + c);
            float4 wb = *(const float4*)(s_wc + o2*68 + c);
            #pragma unroll
            for (int j = 0; j < 4; j++) {
                float4 x = *(const float4*)(bA + j*192 + c);
                c1[j] += wa.x*x.x + wa.y*x.y + wa.z*x.z + wa.w*x.w;
                c2[j] += wb.x*x.x + wb.y*x.y + wb.z*x.z + wb.w*x.w;
            }
        }
        __syncwarp();
        #pragma unroll
        for (int j = 0; j < 4; j++) {
            bA[j*192 + 64 + o1] = fmaxf(c1[j], 0.f);
            bA[j*192 + 64 + o2] = fmaxf(c2[j], 0.f);
        }

        // --- flo = relu(w_flow @ flow + b) ---
        float f0[4], f1[4], f2[4];
        #pragma unroll
        for (int j = 0; j < 4; j++) {
            f0[j] = __ldg(fbase + 3*j + 0);
            f1[j] = __ldg(fbase + 3*j + 1);
            f2[j] = __ldg(fbase + 3*j + 2);
            bA[j*192 + 128 + o1] = fmaxf(s_bias[256+o1] + wf0a*f0[j] + wf1a*f1[j] + wf2a*f2[j], 0.f);
            bA[j*192 + 128 + o2] = fmaxf(s_bias[256+o2] + wf0b*f0[j] + wf1b*f1[j] + wf2b*f2[j], 0.f);
        }
        __syncwarp();

        // --- mf = relu(w_me @ [cor, flo] + b)  (inputs at bA[64..191]) ---
        float m1[4], m2[4];
        #pragma unroll
        for (int j = 0; j < 4; j++) { m1[j] = s_bias[320+o1]; m2[j] = s_bias[320+o2]; }
        #pragma unroll
        for (int c = 0; c < 128; c += 4) {
            float4 wa = *(const float4*)(s_wme + o1*132 + c);
            float4 wb = *(const float4*)(s_wme + o2*132 + c);
            #pragma unroll
            for (int j = 0; j < 4; j++) {
                float4 x = *(const float4*)(bA + j*192 + 64 + c);
                m1[j] += wa.x*x.x + wa.y*x.y + wa.z*x.z + wa.w*x.w;
                m2[j] += wb.x*x.x + wb.y*x.y + wb.z*x.z + wb.w*x.w;
            }
        }
        __syncwarp();

        // --- build hx = [net | inp | mf(61) flow(3)]: 512 elems, 8 iters x 2 ---
        #pragma unroll
        for (int t = 0; t < 8; t++) {
            int idx = t*32 + lane;
            int c = idx >> 2, j = idx & 3;
            bA[j*192 + c]      = __ldg(nbase + (size_t)c*NN + j);
            bA[j*192 + 64 + c] = __ldg(ibase + (size_t)c*NN + j);
        }
        #pragma unroll
        for (int j = 0; j < 4; j++) {
            bA[j*192 + 128 + o1] = fmaxf(m1[j], 0.f);
            if (o2 < 61) bA[j*192 + 128 + o2] = fmaxf(m2[j], 0.f);
            if (lane < 3) bA[j*192 + 189 + lane] = (lane == 0) ? f0[j] : (lane == 1 ? f1[j] : f2[j]);
        }
        __syncwarp();

        // --- z, r (fused 64x192 mvs) ---
        float z1[4], z2[4], r1[4], r2[4];
        #pragma unroll
        for (int j = 0; j < 4; j++) {
            z1[j] = s_bias[o1];    z2[j] = s_bias[o2];
            r1[j] = s_bias[64+o1]; r2[j] = s_bias[64+o2];
        }
        #pragma unroll
        for (int c = 0; c < 192; c += 4) {
            float4 wza = *(const float4*)(s_wz + o1*196 + c);
            float4 wzb = *(const float4*)(s_wz + o2*196 + c);
            float4 wra = *(const float4*)(s_wr + o1*196 + c);
            float4 wrb = *(const float4*)(s_wr + o2*196 + c);
            #pragma unroll
            for (int j = 0; j < 4; j++) {
                float4 x = *(const float4*)(bA + j*192 + c);
                z1[j] += wza.x*x.x + wza.y*x.y + wza.z*x.z + wza.w*x.w;
                z2[j] += wzb.x*x.x + wzb.y*x.y + wzb.z*x.z + wzb.w*x.w;
                r1[j] += wra.x*x.x + wra.y*x.y + wra.z*x.z + wra.w*x.w;
                r2[j] += wrb.x*x.x + wrb.y*x.y + wrb.z*x.z + wrb.w*x.w;
            }
        }
        float net1[4], net2[4];
        #pragma unroll
        for (int j = 0; j < 4; j++) {
            z1[j] = 1.f / (1.f + __expf(-z1[j]));
            z2[j] = 1.f / (1.f + __expf(-z2[j]));
            r1[j] = 1.f / (1.f + __expf(-r1[j]));
            r2[j] = 1.f / (1.f + __expf(-r2[j]));
            net1[j] = bA[j*192 + o1];
            net2[j] = bA[j*192 + o2];
        }
        __syncwarp();
        #pragma unroll
        for (int j = 0; j < 4; j++) {
            bA[j*192 + o1] = r1[j] * net1[j];
            bA[j*192 + o2] = r2[j] * net2[j];
        }
        __syncwarp();

        // --- q = tanh(wq @ [r*net | x]) ---
        float q1[4], q2[4];
        #pragma unroll
        for (int j = 0; j < 4; j++) { q1[j] = s_bias[128+o1]; q2[j] = s_bias[128+o2]; }
        #pragma unroll
        for (int c = 0; c < 192; c += 4) {
            float4 wa = *(const float4*)(s_wq + o1*196 + c);
            float4 wb = *(const float4*)(s_wq + o2*196 + c);
            #pragma unroll
            for (int j = 0; j < 4; j++) {
                float4 x = *(const float4*)(bA + j*192 + c);
                q1[j] += wa.x*x.x + wa.y*x.y + wa.z*x.z + wa.w*x.w;
                q2[j] += wb.x*x.x + wb.y*x.y + wb.z*x.z + wb.w*x.w;
            }
        }
        // --- net_new = (1-z)*net + z*q ---
        float* ft = g_featT + (size_t)p0 * 64;
        #pragma unroll
        for (int j = 0; j < 4; j++) {
            float nn1 = (1.f - z1[j]) * net1[j] + z1[j] * tanhf(q1[j]);
            float nn2 = (1.f - z2[j]) * net2[j] + z2[j] * tanhf(q2[j]);
            ft[j*64 + o1] = nn1;
            ft[j*64 + o2] = nn2;
        }
        __syncwarp();
    }
}

// ---------------------------------------------------------------------------
// Kernel 2: per 64-point tile — transpose net_new into d_out (B,64,N) layout
// and precompute g1 = W_sc1[:, :64] @ net_new + b_sc1  (row-major B*N x 64)
// ---------------------------------------------------------------------------
__global__ __launch_bounds__(256) void k2_kernel(
    const float* __restrict__ w_sc1, const float* __restrict__ b_sc1,
    float* __restrict__ out_net)
{
    __shared__ float s_w[64*68];
    __shared__ float s_b[64];
    __shared__ float s_ft[64*68];

    const int tid = threadIdx.x;
    for (int i = tid; i < 64*64; i += 256) { int o=i>>6, c=i&63; s_w[o*68+c] = w_sc1[o*67+c]; }
    if (tid < 64) s_b[tid] = b_sc1[tid];

    const int tile = blockIdx.x;                 // one tile (64 points) per block
    const int P0 = tile * 64;
    const int b  = P0 >> 15;
    const int n0 = P0 & (NN - 1);

    // load 64 pts x 64 ch, vectorized
    const float4* src = (const float4*)(g_featT + (size_t)P0 * 64);
    for (int i = tid; i < 64*16; i += 256) {
        int pl = i >> 4, c4 = i & 15;
        *(float4*)(s_ft + pl*68 + c4*4) = src[pl*16 + c4];
    }
    __syncthreads();

    // transposed store into d_out (B,64,N)
    for (int i = tid; i < 4096; i += 256) {
        int c = i >> 6, pl = i & 63;
        out_net[((size_t)b*64 + c)*NN + n0 + pl] = s_ft[pl*68 + c];
    }

    // g1 (warp per point)
    const int warp = tid >> 5, lane = tid & 31;
    const int o1 = lane, o2 = lane + 32;
    for (int pl = warp; pl < 64; pl += 8) {
        float a1 = s_b[o1], a2 = s_b[o2];
        #pragma unroll
        for (int c = 0; c < 64; c += 4) {
            float4 x  = *(const float4*)(s_ft + pl*68 + c);
            float4 wa = *(const float4*)(s_w + o1*68 + c);
            float4 wb = *(const float4*)(s_w + o2*68 + c);
            a1 += wa.x*x.x + wa.y*x.y + wa.z*x.z + wa.w*x.w;
            a2 += wb.x*x.x + wb.y*x.y + wb.z*x.z + wb.w*x.w;
        }
        float* g = g_g1 + (size_t)(P0 + pl) * 64;
        g[o1] = a1; g[o2] = a2;
    }
}

// ---------------------------------------------------------------------------
// Phase 3: SetConv gather/max + sc2/sc3 + FlowHead. Warp handles 2 points.
// ---------------------------------------------------------------------------
__global__ __launch_bounds__(256) void phase3_kernel(
    const int* __restrict__ edges, const float* __restrict__ efeat,
    const float* __restrict__ w_sc1,
    const float* __restrict__ w_sc2, const float* __restrict__ b_sc2,
    const float* __restrict__ w_sc3, const float* __restrict__ b_sc3,
    const float* __restrict__ w_fh1, const float* __restrict__ b_fh1,
    const float* __restrict__ w_out1, const float* __restrict__ b_out1,
    const float* __restrict__ w_out2, const float* __restrict__ b_out2,
    float* __restrict__ out_delta)
{
    extern __shared__ float sm[];
    float* s_w2   = sm;                 // 64*68
    float* s_w3   = s_w2  + 64*68;
    float* s_wf   = s_w3  + 64*68;
    float* s_wo1  = s_wf  + 64*68;      // 64*132
    float* s_we   = s_wo1 + 64*132;     // 64*4 (ef columns of w_sc1)
    float* s_wo2  = s_we  + 256;        // 3*64
    float* s_bias = s_wo2 + 192;        // 288: [b_sc2][b_sc3][b_fh1][b_out1][b_out2]
    float* s_buf  = s_bias + 288;       // 16 pts * 256: [bnn 64 | sc/cat 128 | btmp 64]

    const int tid = threadIdx.x;
    for (int i = tid; i < 64*64; i += 256) {
        int o = i >> 6, c = i & 63;
        s_w2[o*68+c] = w_sc2[i]; s_w3[o*68+c] = w_sc3[i]; s_wf[o*68+c] = w_fh1[i];
    }
    for (int i = tid; i < 64*128; i += 256) { int o=i>>7, c=i&127; s_wo1[o*132+c] = w_out1[i]; }
    for (int i = tid; i < 64*3; i += 256)   { int o=i/3, c=i-o*3;  s_we[o*4+c] = w_sc1[o*67 + 64 + c]; }
    for (int i = tid; i < 192; i += 256)    s_wo2[i] = w_out2[i];
    if (tid < 64) {
        s_bias[tid]     = b_sc2[tid];
        s_bias[64+tid]  = b_sc3[tid];
        s_bias[128+tid] = b_fh1[tid];
        s_bias[192+tid] = b_out1[tid];
    }
    if (tid < 3) s_bias[256+tid] = b_out2[tid];
    __syncthreads();

    const int warp = tid >> 5, lane = tid & 31;
    const int o1 = lane, o2 = lane + 32;
    float* B0 = s_buf + warp * 2 * 256;

    const float we0a = s_we[o1*4], we1a = s_we[o1*4+1], we2a = s_we[o1*4+2];
    const float we0b = s_we[o2*4], we1b = s_we[o2*4+1], we2b = s_we[o2*4+2];

    for (int task = blockIdx.x*8 + warp; task < BN/2; task += gridDim.x*8) {
        const int p0 = task * 2;
        const int b  = p0 >> 15;

        // net_new rows into bnn
        #pragma unroll
        for (int j = 0; j < 2; j++) {
            const float* fr = g_featT + (size_t)(p0 + j) * 64;
            B0[j*256 + o1] = fr[o1];
            B0[j*256 + o2] = fr[o2];
        }

        // gather + max over K neighbors: s = relu(max_k (g1[e_k] + W_e @ ef_k))
        float m1[2] = {-3.0e38f, -3.0e38f}, m2[2] = {-3.0e38f, -3.0e38f};
        #pragma unroll
        for (int j = 0; j < 2; j++) {
            const int*   ep  = edges + (size_t)(p0 + j) * KK;
            const float* efp = efeat + (size_t)(p0 + j) * KK * 3;
            #pragma unroll
            for (int k = 0; k < KK; k++) {
                int e = __ldg(ep + k);
                float e0 = __ldg(efp + 3*k + 0);
                float e1 = __ldg(efp + 3*k + 1);
                float e2 = __ldg(efp + 3*k + 2);
                const float* g1r = g_g1 + ((size_t)b*NN + e) * 64;
                float v1 = __ldg(g1r + o1) + we0a*e0 + we1a*e1 + we2a*e2;
                float v2 = __ldg(g1r + o2) + we0b*e0 + we1b*e1 + we2b*e2;
                m1[j] = fmaxf(m1[j], v1);
                m2[j] = fmaxf(m2[j], v2);
            }
        }
        #pragma unroll
        for (int j = 0; j < 2; j++) {
            B0[j*256 + 192 + o1] = fmaxf(m1[j], 0.f);
            B0[j*256 + 192 + o2] = fmaxf(m2[j], 0.f);
        }
        __syncwarp();

        // sc2
        float t1[2], t2[2];
        #pragma unroll
        for (int j = 0; j < 2; j++) { t1[j] = s_bias[o1]; t2[j] = s_bias[o2]; }
        #pragma unroll
        for (int c = 0; c < 64; c += 4) {
            float4 wa = *(const float4*)(s_w2 + o1*68 + c);
            float4 wb = *(const float4*)(s_w2 + o2*68 + c);
            #pragma unroll
            for (int j = 0; j < 2; j++) {
                float4 x = *(const float4*)(B0 + j*256 + 192 + c);
                t1[j] += wa.x*x.x + wa.y*x.y + wa.z*x.z + wa.w*x.w;
                t2[j] += wb.x*x.x + wb.y*x.y + wb.z*x.z + wb.w*x.w;
            }
        }
        __syncwarp();
        #pragma unroll
        for (int j = 0; j < 2; j++) {
            B0[j*256 + 192 + o1] = fmaxf(t1[j], 0.f);
            B0[j*256 + 192 + o2] = fmaxf(t2[j], 0.f);
        }
        __syncwarp();

        // sc3 (over btmp) + fh1 (over bnn), fused c-loop
        float u1[2], u2[2], h1[2], h2[2];
        #pragma unroll
        for (int j = 0; j < 2; j++) {
            u1[j] = s_bias[64+o1];  u2[j] = s_bias[64+o2];
            h1[j] = s_bias[128+o1]; h2[j] = s_bias[128+o2];
        }
        #pragma unroll
        for (int c = 0; c < 64; c += 4) {
            float4 w3a = *(const float4*)(s_w3 + o1*68 + c);
            float4 w3b = *(const float4*)(s_w3 + o2*68 + c);
            float4 wfa = *(const float4*)(s_wf + o1*68 + c);
            float4 wfb = *(const float4*)(s_wf + o2*68 + c);
            #pragma unroll
            for (int j = 0; j < 2; j++) {
                float4 x = *(const float4*)(B0 + j*256 + 192 + c);
                float4 y = *(const float4*)(B0 + j*256 + c);
                u1[j] += w3a.x*x.x + w3a.y*x.y + w3a.z*x.z + w3a.w*x.w;
                u2[j] += w3b.x*x.x + w3b.y*x.y + w3b.z*x.z + w3b.w*x.w;
                h1[j] += wfa.x*y.x + wfa.y*y.y + wfa.z*y.z + wfa.w*y.w;
                h2[j] += wfb.x*y.x + wfb.y*y.y + wfb.z*y.z + wfb.w*y.w;
            }
        }
        __syncwarp();
        #pragma unroll
        for (int j = 0; j < 2; j++) {
            B0[j*256 + 64 + o1]  = fmaxf(u1[j], 0.f);   // sc channels 0..63
            B0[j*256 + 64 + o2]  = fmaxf(u2[j], 0.f);
            B0[j*256 + 128 + o1] = h1[j];               // fh1 channels 64..127
            B0[j*256 + 128 + o2] = h2[j];
        }
        __syncwarp();

        // out1 = relu(w_out1 @ [sc | fh1] + b)
        float v1[2], v2[2];
        #pragma unroll
        for (int j = 0; j < 2; j++) { v1[j] = s_bias[192+o1]; v2[j] = s_bias[192+o2]; }
        #pragma unroll
        for (int c = 0; c < 128; c += 4) {
            float4 wa = *(const float4*)(s_wo1 + o1*132 + c);
            float4 wb = *(const float4*)(s_wo1 + o2*132 + c);
            #pragma unroll
            for (int j = 0; j < 2; j++) {
                float4 x = *(const float4*)(B0 + j*256 + 64 + c);
                v1[j] += wa.x*x.x + wa.y*x.y + wa.z*x.z + wa.w*x.w;
                v2[j] += wb.x*x.x + wb.y*x.y + wb.z*x.z + wb.w*x.w;
            }
        }
        #pragma unroll
        for (int j = 0; j < 2; j++) { v1[j] = fmaxf(v1[j], 0.f); v2[j] = fmaxf(v2[j], 0.f); }

        // out2: 3 outputs via warp reduction over the 64 channels held in regs
        #pragma unroll
        for (int jj = 0; jj < 3; jj++) {
            #pragma unroll
            for (int j = 0; j < 2; j++) {
                float partial = s_wo2[jj*64 + o1] * v1[j] + s_wo2[jj*64 + o2] * v2[j];
                #pragma unroll
                for (int sft = 16; sft > 0; sft >>= 1)
                    partial += __shfl_xor_sync(0xffffffffu, partial, sft);
                if (lane == 0)
                    out_delta[(size_t)(p0 + j)*3 + jj] = partial + s_bias[256 + jj];
            }
        }
        __syncwarp();
    }
}

// ---------------------------------------------------------------------------
extern "C" void kernel_launch(void* const* d_in, const int* in_sizes, int n_in,
                              void* d_out, int out_size)
{
    const float* net    = (const float*)d_in[0];
    const float* inp    = (const float*)d_in[1];
    const float* corr   = (const float*)d_in[2];
    const float* flow   = (const float*)d_in[3];
    const int*   edges  = (const int*)  d_in[4];
    const float* efeat  = (const float*)d_in[5];
    const float* w_corr = (const float*)d_in[6];
    const float* b_corr = (const float*)d_in[7];
    const float* w_flow = (const float*)d_in[8];
    const float* b_flow = (const float*)d_in[9];
    const float* w_me   = (const float*)d_in[10];
    const float* b_me   = (const float*)d_in[11];
    const float* wz     = (const float*)d_in[12];
    const float* bz     = (const float*)d_in[13];
    const float* wr     = (const float*)d_in[14];
    const float* br     = (const float*)d_in[15];
    const float* wq     = (const float*)d_in[16];
    const float* bq     = (const float*)d_in[17];
    const float* w_fh1  = (const float*)d_in[18];
    const float* b_fh1  = (const float*)d_in[19];
    const float* w_sc1  = (const float*)d_in[20];
    const float* b_sc1  = (const float*)d_in[21];
    const float* w_sc2  = (const float*)d_in[22];
    const float* b_sc2  = (const float*)d_in[23];
    const float* w_sc3  = (const float*)d_in[24];
    const float* b_sc3  = (const float*)d_in[25];
    const float* w_out1 = (const float*)d_in[26];
    const float* b_out1 = (const float*)d_in[27];
    const float* w_out2 = (const float*)d_in[28];
    const float* b_out2 = (const float*)d_in[29];

    float* out       = (float*)d_out;
    float* out_net   = out;                         // (B,64,N)
    float* out_delta = out + (size_t)BB*64*NN;      // (B,N,3)

    const size_t SMEM1 = (size_t)(64*196*3 + 61*132 + 64*68 + 384 + 32*192) * sizeof(float);
    const size_t SMEM3 = (size_t)(64*68*3 + 64*132 + 256 + 192 + 288 + 16*256) * sizeof(float);

    cudaFuncSetAttribute(phase1_kernel, cudaFuncAttributeMaxDynamicSharedMemorySize, (int)SMEM1);
    cudaFuncSetAttribute(phase3_kernel, cudaFuncAttributeMaxDynamicSharedMemorySize, (int)SMEM3);

    // GB300 has 152 SMs: phase1 = 1 block/SM (226KB smem), phase3 = 2 blocks/SM
    phase1_kernel<<<152, 256, SMEM1>>>(net, inp, corr, flow,
                                       w_corr, b_corr, w_flow, b_flow, w_me, b_me,
                                       wz, bz, wr, br, wq, bq);
    k2_kernel<<<BN/64, 256>>>(w_sc1, b_sc1, out_net);
    phase3_kernel<<<304, 256, SMEM3>>>(edges, efeat, w_sc1,
                                       w_sc2, b_sc2, w_sc3, b_sc3,
                                       w_fh1, b_fh1, w_out1, b_out1,
                                       w_out2, b_out2, out_delta);
}

// round 10
// speedup vs baseline: 1.4372x; 1.4372x over previous
#include <cuda_runtime.h>
#include <cstdint>

#define BB 2
#define NN 32768
#define KK 16
#define BN (BB*NN)

// Scratch (device globals; no allocation allowed)
__device__ float g_featT[(size_t)BN*64];   // net_new, (B*N, 64) row-major
__device__ float g_g1[(size_t)BN*64];      // W_sc1[:, :64] @ net_new + b_sc1
__device__ float g_motion[(size_t)BN*64];  // [mf(61)|flow(3)] per point, row-major

// ---------------------------------------------------------------------------
// ME kernel: MotionEncoder. Warp per 4 points. 75KB smem -> 3 blocks/SM.
// ---------------------------------------------------------------------------
__global__ __launch_bounds__(256) void me_kernel(
    const float* __restrict__ corr, const float* __restrict__ flow,
    const float* __restrict__ w_corr, const float* __restrict__ b_corr,
    const float* __restrict__ w_flow, const float* __restrict__ b_flow,
    const float* __restrict__ w_me, const float* __restrict__ b_me)
{
    extern __shared__ float sm[];
    float* s_wc   = sm;                 // 64*68
    float* s_wme  = s_wc + 64*68;       // 61*132
    float* s_bias = s_wme + 61*132;     // 192: [b_corr][b_flow][b_me]
    float* s_buf  = s_bias + 192;       // 8 warps * 4 pts * 192

    const int tid = threadIdx.x;
    for (int i = tid; i < 64*64; i += 256) { int o=i>>6, c=i&63; s_wc[o*68+c]=w_corr[i]; }
    for (int i = tid; i < 61*128; i += 256) { int o=i/128, c=i-o*128; s_wme[o*132+c]=w_me[i]; }
    if (tid < 64) {
        s_bias[tid]     = b_corr[tid];
        s_bias[64+tid]  = b_flow[tid];
        s_bias[128+tid] = (tid < 61) ? b_me[tid] : 0.f;
    }
    __syncthreads();

    const int warp = tid >> 5, lane = tid & 31;
    const int o1 = lane, o2 = lane + 32;
    float* bA = s_buf + warp * 4 * 192;   // per point: [corr 0..63 | cor 64..127 | flo 128..191]

    const float wf0a = __ldg(w_flow + o1*3 + 0), wf1a = __ldg(w_flow + o1*3 + 1), wf2a = __ldg(w_flow + o1*3 + 2);
    const float wf0b = __ldg(w_flow + o2*3 + 0), wf1b = __ldg(w_flow + o2*3 + 1), wf2b = __ldg(w_flow + o2*3 + 2);

    for (int task = blockIdx.x*8 + warp; task < BN/4; task += gridDim.x*8) {
        const int p0 = task * 4;
        const int b  = p0 >> 15;
        const int n0 = p0 & (NN - 1);
        const float* cbase = corr + (size_t)b*64*NN + n0;
        const float* fbase = flow + ((size_t)b*NN + n0)*3;

        #pragma unroll
        for (int t = 0; t < 8; t++) {
            int idx = t*32 + lane;
            int c = idx >> 2, j = idx & 3;
            bA[j*192 + c] = __ldg(cbase + (size_t)c*NN + j);
        }
        __syncwarp();

        // cor = relu(w_corr @ corr + b)
        float c1[4], c2[4];
        #pragma unroll
        for (int j = 0; j < 4; j++) { c1[j] = s_bias[o1]; c2[j] = s_bias[o2]; }
        #pragma unroll
        for (int c = 0; c < 64; c += 4) {
            float4 wa = *(const float4*)(s_wc + o1*68 + c);
            float4 wb = *(const float4*)(s_wc + o2*68 + c);
            #pragma unroll
            for (int j = 0; j < 4; j++) {
                float4 x = *(const float4*)(bA + j*192 + c);
                c1[j] += wa.x*x.x + wa.y*x.y + wa.z*x.z + wa.w*x.w;
                c2[j] += wb.x*x.x + wb.y*x.y + wb.z*x.z + wb.w*x.w;
            }
        }
        __syncwarp();

        // flo = relu(w_flow @ flow + b); stash cor too
        float f0[4], f1[4], f2[4];
        #pragma unroll
        for (int j = 0; j < 4; j++) {
            f0[j] = __ldg(fbase + 3*j + 0);
            f1[j] = __ldg(fbase + 3*j + 1);
            f2[j] = __ldg(fbase + 3*j + 2);
            bA[j*192 + 64 + o1]  = fmaxf(c1[j], 0.f);
            bA[j*192 + 64 + o2]  = fmaxf(c2[j], 0.f);
            bA[j*192 + 128 + o1] = fmaxf(s_bias[64+o1] + wf0a*f0[j] + wf1a*f1[j] + wf2a*f2[j], 0.f);
            bA[j*192 + 128 + o2] = fmaxf(s_bias[64+o2] + wf0b*f0[j] + wf1b*f1[j] + wf2b*f2[j], 0.f);
        }
        __syncwarp();

        // mf = relu(w_me @ [cor|flo] + b)
        float m1[4], m2[4];
        #pragma unroll
        for (int j = 0; j < 4; j++) { m1[j] = s_bias[128+o1]; m2[j] = s_bias[128+o2]; }
        #pragma unroll
        for (int c = 0; c < 128; c += 4) {
            float4 wa = *(const float4*)(s_wme + o1*132 + c);
            float4 wb = *(const float4*)(s_wme + o2*132 + c);
            #pragma unroll
            for (int j = 0; j < 4; j++) {
                float4 x = *(const float4*)(bA + j*192 + 64 + c);
                m1[j] += wa.x*x.x + wa.y*x.y + wa.z*x.z + wa.w*x.w;
                m2[j] += wb.x*x.x + wb.y*x.y + wb.z*x.z + wb.w*x.w;
            }
        }

        // motion = [mf(61) | flow(3)], row-major per point
        float* mo = g_motion + (size_t)p0 * 64;
        #pragma unroll
        for (int j = 0; j < 4; j++) {
            mo[j*64 + o1] = fmaxf(m1[j], 0.f);
            mo[j*64 + o2] = (o2 < 61) ? fmaxf(m2[j], 0.f)
                          : (o2 == 61 ? f0[j] : (o2 == 62 ? f1[j] : f2[j]));
        }
        __syncwarp();
    }
}

// ---------------------------------------------------------------------------
// GRU kernel: 512 threads (16 warps/SM), PT=4, 200KB smem (wz/wr/wq only).
// ---------------------------------------------------------------------------
__global__ __launch_bounds__(512, 1) void gru_kernel(
    const float* __restrict__ net, const float* __restrict__ inp,
    const float* __restrict__ wz, const float* __restrict__ bz,
    const float* __restrict__ wr, const float* __restrict__ br,
    const float* __restrict__ wq, const float* __restrict__ bq)
{
    extern __shared__ float sm[];
    float* s_wz   = sm;                 // 64*196
    float* s_wr   = s_wz + 64*196;
    float* s_wq   = s_wr + 64*196;
    float* s_bias = s_wq + 64*196;      // 192: [bz][br][bq]
    float* s_buf  = s_bias + 192;       // 16 warps * 4 pts * 192

    const int tid = threadIdx.x;
    for (int i = tid; i < 64*192; i += 512) {
        int o = i / 192, c = i - o*192;
        s_wz[o*196+c] = wz[i]; s_wr[o*196+c] = wr[i]; s_wq[o*196+c] = wq[i];
    }
    if (tid < 64) {
        s_bias[tid]     = bz[tid];
        s_bias[64+tid]  = br[tid];
        s_bias[128+tid] = bq[tid];
    }
    __syncthreads();

    const int warp = tid >> 5, lane = tid & 31;
    const int o1 = lane, o2 = lane + 32;
    float* bA = s_buf + warp * 4 * 192;   // hx per point: [net 0..63 | inp 64..127 | motion 128..191]

    for (int task = blockIdx.x*16 + warp; task < BN/4; task += gridDim.x*16) {
        const int p0 = task * 4;
        const int b  = p0 >> 15;
        const int n0 = p0 & (NN - 1);
        const float* nbase = net + (size_t)b*64*NN + n0;
        const float* ibase = inp + (size_t)b*64*NN + n0;
        const float* mbase = g_motion + (size_t)p0 * 64;

        #pragma unroll
        for (int t = 0; t < 8; t++) {
            int idx = t*32 + lane;
            int c = idx >> 2, j = idx & 3;
            bA[j*192 + c]      = __ldg(nbase + (size_t)c*NN + j);
            bA[j*192 + 64 + c] = __ldg(ibase + (size_t)c*NN + j);
        }
        #pragma unroll
        for (int t = 0; t < 2; t++) {
            int idx = t*32 + lane;
            int j = idx >> 4, c4 = idx & 15;
            *(float4*)(bA + j*192 + 128 + c4*4) = *(const float4*)(mbase + j*64 + c4*4);
        }
        __syncwarp();

        // z, r (fused 64x192 mvs)
        float z1[4], z2[4], r1[4], r2[4];
        #pragma unroll
        for (int j = 0; j < 4; j++) {
            z1[j] = s_bias[o1];    z2[j] = s_bias[o2];
            r1[j] = s_bias[64+o1]; r2[j] = s_bias[64+o2];
        }
        #pragma unroll
        for (int c = 0; c < 192; c += 4) {
            float4 wza = *(const float4*)(s_wz + o1*196 + c);
            float4 wzb = *(const float4*)(s_wz + o2*196 + c);
            float4 wra = *(const float4*)(s_wr + o1*196 + c);
            float4 wrb = *(const float4*)(s_wr + o2*196 + c);
            #pragma unroll
            for (int j = 0; j < 4; j++) {
                float4 x = *(const float4*)(bA + j*192 + c);
                z1[j] += wza.x*x.x + wza.y*x.y + wza.z*x.z + wza.w*x.w;
                z2[j] += wzb.x*x.x + wzb.y*x.y + wzb.z*x.z + wzb.w*x.w;
                r1[j] += wra.x*x.x + wra.y*x.y + wra.z*x.z + wra.w*x.w;
                r2[j] += wrb.x*x.x + wrb.y*x.y + wrb.z*x.z + wrb.w*x.w;
            }
        }
        float net1[4], net2[4];
        #pragma unroll
        for (int j = 0; j < 4; j++) {
            z1[j] = 1.f / (1.f + __expf(-z1[j]));
            z2[j] = 1.f / (1.f + __expf(-z2[j]));
            r1[j] = 1.f / (1.f + __expf(-r1[j]));
            r2[j] = 1.f / (1.f + __expf(-r2[j]));
            net1[j] = bA[j*192 + o1];
            net2[j] = bA[j*192 + o2];
        }
        __syncwarp();
        #pragma unroll
        for (int j = 0; j < 4; j++) {
            bA[j*192 + o1] = r1[j] * net1[j];
            bA[j*192 + o2] = r2[j] * net2[j];
        }
        __syncwarp();

        // q = tanh(wq @ [r*net | x])
        float q1[4], q2[4];
        #pragma unroll
        for (int j = 0; j < 4; j++) { q1[j] = s_bias[128+o1]; q2[j] = s_bias[128+o2]; }
        #pragma unroll
        for (int c = 0; c < 192; c += 4) {
            float4 wa = *(const float4*)(s_wq + o1*196 + c);
            float4 wb = *(const float4*)(s_wq + o2*196 + c);
            #pragma unroll
            for (int j = 0; j < 4; j++) {
                float4 x = *(const float4*)(bA + j*192 + c);
                q1[j] += wa.x*x.x + wa.y*x.y + wa.z*x.z + wa.w*x.w;
                q2[j] += wb.x*x.x + wb.y*x.y + wb.z*x.z + wb.w*x.w;
            }
        }
        float* ft = g_featT + (size_t)p0 * 64;
        #pragma unroll
        for (int j = 0; j < 4; j++) {
            ft[j*64 + o1] = (1.f - z1[j]) * net1[j] + z1[j] * tanhf(q1[j]);
            ft[j*64 + o2] = (1.f - z2[j]) * net2[j] + z2[j] * tanhf(q2[j]);
        }
        __syncwarp();
    }
}

// ---------------------------------------------------------------------------
// Kernel 2: transpose net_new into d_out (B,64,N) + precompute g1
// ---------------------------------------------------------------------------
__global__ __launch_bounds__(256) void k2_kernel(
    const float* __restrict__ w_sc1, const float* __restrict__ b_sc1,
    float* __restrict__ out_net)
{
    __shared__ float s_w[64*68];
    __shared__ float s_b[64];
    __shared__ float s_ft[64*68];

    const int tid = threadIdx.x;
    for (int i = tid; i < 64*64; i += 256) { int o=i>>6, c=i&63; s_w[o*68+c] = w_sc1[o*67+c]; }
    if (tid < 64) s_b[tid] = b_sc1[tid];

    const int tile = blockIdx.x;
    const int P0 = tile * 64;
    const int b  = P0 >> 15;
    const int n0 = P0 & (NN - 1);

    const float4* src = (const float4*)(g_featT + (size_t)P0 * 64);
    for (int i = tid; i < 64*16; i += 256) {
        int pl = i >> 4, c4 = i & 15;
        *(float4*)(s_ft + pl*68 + c4*4) = src[pl*16 + c4];
    }
    __syncthreads();

    for (int i = tid; i < 4096; i += 256) {
        int c = i >> 6, pl = i & 63;
        out_net[((size_t)b*64 + c)*NN + n0 + pl] = s_ft[pl*68 + c];
    }

    const int warp = tid >> 5, lane = tid & 31;
    const int o1 = lane, o2 = lane + 32;
    for (int pl = warp; pl < 64; pl += 8) {
        float a1 = s_b[o1], a2 = s_b[o2];
        #pragma unroll
        for (int c = 0; c < 64; c += 4) {
            float4 x  = *(const float4*)(s_ft + pl*68 + c);
            float4 wa = *(const float4*)(s_w + o1*68 + c);
            float4 wb = *(const float4*)(s_w + o2*68 + c);
            a1 += wa.x*x.x + wa.y*x.y + wa.z*x.z + wa.w*x.w;
            a2 += wb.x*x.x + wb.y*x.y + wb.z*x.z + wb.w*x.w;
        }
        float* g = g_g1 + (size_t)(P0 + pl) * 64;
        g[o1] = a1; g[o2] = a2;
    }
}

// ---------------------------------------------------------------------------
// Phase 3: SetConv gather/max + sc2/sc3 + FlowHead. Warp handles 2 points.
// ---------------------------------------------------------------------------
__global__ __launch_bounds__(256) void phase3_kernel(
    const int* __restrict__ edges, const float* __restrict__ efeat,
    const float* __restrict__ w_sc1,
    const float* __restrict__ w_sc2, const float* __restrict__ b_sc2,
    const float* __restrict__ w_sc3, const float* __restrict__ b_sc3,
    const float* __restrict__ w_fh1, const float* __restrict__ b_fh1,
    const float* __restrict__ w_out1, const float* __restrict__ b_out1,
    const float* __restrict__ w_out2, const float* __restrict__ b_out2,
    float* __restrict__ out_delta)
{
    extern __shared__ float sm[];
    float* s_w2   = sm;                 // 64*68
    float* s_w3   = s_w2  + 64*68;
    float* s_wf   = s_w3  + 64*68;
    float* s_wo1  = s_wf  + 64*68;      // 64*132
    float* s_we   = s_wo1 + 64*132;     // 64*4
    float* s_wo2  = s_we  + 256;        // 3*64
    float* s_bias = s_wo2 + 192;        // 288
    float* s_buf  = s_bias + 288;       // 16 pts * 256

    const int tid = threadIdx.x;
    for (int i = tid; i < 64*64; i += 256) {
        int o = i >> 6, c = i & 63;
        s_w2[o*68+c] = w_sc2[i]; s_w3[o*68+c] = w_sc3[i]; s_wf[o*68+c] = w_fh1[i];
    }
    for (int i = tid; i < 64*128; i += 256) { int o=i>>7, c=i&127; s_wo1[o*132+c] = w_out1[i]; }
    for (int i = tid; i < 64*3; i += 256)   { int o=i/3, c=i-o*3;  s_we[o*4+c] = w_sc1[o*67 + 64 + c]; }
    for (int i = tid; i < 192; i += 256)    s_wo2[i] = w_out2[i];
    if (tid < 64) {
        s_bias[tid]     = b_sc2[tid];
        s_bias[64+tid]  = b_sc3[tid];
        s_bias[128+tid] = b_fh1[tid];
        s_bias[192+tid] = b_out1[tid];
    }
    if (tid < 3) s_bias[256+tid] = b_out2[tid];
    __syncthreads();

    const int warp = tid >> 5, lane = tid & 31;
    const int o1 = lane, o2 = lane + 32;
    float* B0 = s_buf + warp * 2 * 256;

    const float we0a = s_we[o1*4], we1a = s_we[o1*4+1], we2a = s_we[o1*4+2];
    const float we0b = s_we[o2*4], we1b = s_we[o2*4+1], we2b = s_we[o2*4+2];

    for (int task = blockIdx.x*8 + warp; task < BN/2; task += gridDim.x*8) {
        const int p0 = task * 2;
        const int b  = p0 >> 15;

        #pragma unroll
        for (int j = 0; j < 2; j++) {
            const float* fr = g_featT + (size_t)(p0 + j) * 64;
            B0[j*256 + o1] = fr[o1];
            B0[j*256 + o2] = fr[o2];
        }

        float m1[2] = {-3.0e38f, -3.0e38f}, m2[2] = {-3.0e38f, -3.0e38f};
        #pragma unroll
        for (int j = 0; j < 2; j++) {
            const int*   ep  = edges + (size_t)(p0 + j) * KK;
            const float* efp = efeat + (size_t)(p0 + j) * KK * 3;
            #pragma unroll
            for (int k = 0; k < KK; k++) {
                int e = __ldg(ep + k);
                float e0 = __ldg(efp + 3*k + 0);
                float e1 = __ldg(efp + 3*k + 1);
                float e2 = __ldg(efp + 3*k + 2);
                const float* g1r = g_g1 + ((size_t)b*NN + e) * 64;
                float v1 = __ldg(g1r + o1) + we0a*e0 + we1a*e1 + we2a*e2;
                float v2 = __ldg(g1r + o2) + we0b*e0 + we1b*e1 + we2b*e2;
                m1[j] = fmaxf(m1[j], v1);
                m2[j] = fmaxf(m2[j], v2);
            }
        }
        #pragma unroll
        for (int j = 0; j < 2; j++) {
            B0[j*256 + 192 + o1] = fmaxf(m1[j], 0.f);
            B0[j*256 + 192 + o2] = fmaxf(m2[j], 0.f);
        }
        __syncwarp();

        float t1[2], t2[2];
        #pragma unroll
        for (int j = 0; j < 2; j++) { t1[j] = s_bias[o1]; t2[j] = s_bias[o2]; }
        #pragma unroll
        for (int c = 0; c < 64; c += 4) {
            float4 wa = *(const float4*)(s_w2 + o1*68 + c);
            float4 wb = *(const float4*)(s_w2 + o2*68 + c);
            #pragma unroll
            for (int j = 0; j < 2; j++) {
                float4 x = *(const float4*)(B0 + j*256 + 192 + c);
                t1[j] += wa.x*x.x + wa.y*x.y + wa.z*x.z + wa.w*x.w;
                t2[j] += wb.x*x.x + wb.y*x.y + wb.z*x.z + wb.w*x.w;
            }
        }
        __syncwarp();
        #pragma unroll
        for (int j = 0; j < 2; j++) {
            B0[j*256 + 192 + o1] = fmaxf(t1[j], 0.f);
            B0[j*256 + 192 + o2] = fmaxf(t2[j], 0.f);
        }
        __syncwarp();

        float u1[2], u2[2], h1[2], h2[2];
        #pragma unroll
        for (int j = 0; j < 2; j++) {
            u1[j] = s_bias[64+o1];  u2[j] = s_bias[64+o2];
            h1[j] = s_bias[128+o1]; h2[j] = s_bias[128+o2];
        }
        #pragma unroll
        for (int c = 0; c < 64; c += 4) {
            float4 w3a = *(const float4*)(s_w3 + o1*68 + c);
            float4 w3b = *(const float4*)(s_w3 + o2*68 + c);
            float4 wfa = *(const float4*)(s_wf + o1*68 + c);
            float4 wfb = *(const float4*)(s_wf + o2*68 + c);
            #pragma unroll
            for (int j = 0; j < 2; j++) {
                float4 x = *(const float4*)(B0 + j*256 + 192 + c);
                float4 y = *(const float4*)(B0 + j*256 + c);
                u1[j] += w3a.x*x.x + w3a.y*x.y + w3a.z*x.z + w3a.w*x.w;
                u2[j] += w3b.x*x.x + w3b.y*x.y + w3b.z*x.z + w3b.w*x.w;
                h1[j] += wfa.x*y.x + wfa.y*y.y + wfa.z*y.z + wfa.w*y.w;
                h2[j] += wfb.x*y.x + wfb.y*y.y + wfb.z*y.z + wfb.w*y.w;
            }
        }
        __syncwarp();
        #pragma unroll
        for (int j = 0; j < 2; j++) {
            B0[j*256 + 64 + o1]  = fmaxf(u1[j], 0.f);
            B0[j*256 + 64 + o2]  = fmaxf(u2[j], 0.f);
            B0[j*256 + 128 + o1] = h1[j];
            B0[j*256 + 128 + o2] = h2[j];
        }
        __syncwarp();

        float v1[2], v2[2];
        #pragma unroll
        for (int j = 0; j < 2; j++) { v1[j] = s_bias[192+o1]; v2[j] = s_bias[192+o2]; }
        #pragma unroll
        for (int c = 0; c < 128; c += 4) {
            float4 wa = *(const float4*)(s_wo1 + o1*132 + c);
            float4 wb = *(const float4*)(s_wo1 + o2*132 + c);
            #pragma unroll
            for (int j = 0; j < 2; j++) {
                float4 x = *(const float4*)(B0 + j*256 + 64 + c);
                v1[j] += wa.x*x.x + wa.y*x.y + wa.z*x.z + wa.w*x.w;
                v2[j] += wb.x*x.x + wb.y*x.y + wb.z*x.z + wb.w*x.w;
            }
        }
        #pragma unroll
        for (int j = 0; j < 2; j++) { v1[j] = fmaxf(v1[j], 0.f); v2[j] = fmaxf(v2[j], 0.f); }

        #pragma unroll
        for (int jj = 0; jj < 3; jj++) {
            #pragma unroll
            for (int j = 0; j < 2; j++) {
                float partial = s_wo2[jj*64 + o1] * v1[j] + s_wo2[jj*64 + o2] * v2[j];
                #pragma unroll
                for (int sft = 16; sft > 0; sft >>= 1)
                    partial += __shfl_xor_sync(0xffffffffu, partial, sft);
                if (lane == 0)
                    out_delta[(size_t)(p0 + j)*3 + jj] = partial + s_bias[256 + jj];
            }
        }
        __syncwarp();
    }
}

// ---------------------------------------------------------------------------
extern "C" void kernel_launch(void* const* d_in, const int* in_sizes, int n_in,
                              void* d_out, int out_size)
{
    const float* net    = (const float*)d_in[0];
    const float* inp    = (const float*)d_in[1];
    const float* corr   = (const float*)d_in[2];
    const float* flow   = (const float*)d_in[3];
    const int*   edges  = (const int*)  d_in[4];
    const float* efeat  = (const float*)d_in[5];
    const float* w_corr = (const float*)d_in[6];
    const float* b_corr = (const float*)d_in[7];
    const float* w_flow = (const float*)d_in[8];
    const float* b_flow = (const float*)d_in[9];
    const float* w_me   = (const float*)d_in[10];
    const float* b_me   = (const float*)d_in[11];
    const float* wz     = (const float*)d_in[12];
    const float* bz     = (const float*)d_in[13];
    const float* wr     = (const float*)d_in[14];
    const float* br     = (const float*)d_in[15];
    const float* wq     = (const float*)d_in[16];
    const float* bq     = (const float*)d_in[17];
    const float* w_fh1  = (const float*)d_in[18];
    const float* b_fh1  = (const float*)d_in[19];
    const float* w_sc1  = (const float*)d_in[20];
    const float* b_sc1  = (const float*)d_in[21];
    const float* w_sc2  = (const float*)d_in[22];
    const float* b_sc2  = (const float*)d_in[23];
    const float* w_sc3  = (const float*)d_in[24];
    const float* b_sc3  = (const float*)d_in[25];
    const float* w_out1 = (const float*)d_in[26];
    const float* b_out1 = (const float*)d_in[27];
    const float* w_out2 = (const float*)d_in[28];
    const float* b_out2 = (const float*)d_in[29];

    float* out       = (float*)d_out;
    float* out_net   = out;                         // (B,64,N)
    float* out_delta = out + (size_t)BB*64*NN;      // (B,N,3)

    const size_t SMEM_ME  = (size_t)(64*68 + 61*132 + 192 + 8*4*192) * sizeof(float);
    const size_t SMEM_GRU = (size_t)(64*196*3 + 192 + 16*4*192) * sizeof(float);
    const size_t SMEM3    = (size_t)(64*68*3 + 64*132 + 256 + 192 + 288 + 16*256) * sizeof(float);

    cudaFuncSetAttribute(me_kernel,  cudaFuncAttributeMaxDynamicSharedMemorySize, (int)SMEM_ME);
    cudaFuncSetAttribute(gru_kernel, cudaFuncAttributeMaxDynamicSharedMemorySize, (int)SMEM_GRU);
    cudaFuncSetAttribute(phase3_kernel, cudaFuncAttributeMaxDynamicSharedMemorySize, (int)SMEM3);

    me_kernel<<<456, 256, SMEM_ME>>>(corr, flow, w_corr, b_corr, w_flow, b_flow, w_me, b_me);
    gru_kernel<<<152, 512, SMEM_GRU>>>(net, inp, wz, bz, wr, br, wq, bq);
    k2_kernel<<<BN/64, 256>>>(w_sc1, b_sc1, out_net);
    phase3_kernel<<<304, 256, SMEM3>>>(edges, efeat, w_sc1,
                                       w_sc2, b_sc2, w_sc3, b_sc3,
                                       w_fh1, b_fh1, w_out1, b_out1,
                                       w_out2, b_out2, out_delta);
}